// round 3
// baseline (speedup 1.0000x reference)
#include <cuda_runtime.h>
#include <cstdint>

#define N_NODES  50000
#define N_EDGES  1600000
#define IN_CH    64
#define HID      16
#define NCLS     10
#define L2S      12   // padded row stride for layer-2 (10 -> 12 for 16B alignment)

// ---------------- scratch (device globals; no allocations allowed) ----------
__device__ __align__(16) float g_y1  [N_NODES * HID];   // x @ w_rel1
__device__ __align__(16) float g_agg1[N_NODES * HID];   // x @ w_root1 + b_rel1, then += scatter
__device__ __align__(16) float g_y2  [N_NODES * L2S];   // h @ w_rel2
__device__ __align__(16) float g_agg2[N_NODES * L2S];   // h @ w_root2 + b_rel2, then += scatter
__device__ int g_is64;                                  // edge_index dtype flag

// ---------------- vector reductions (sm_90+ PTX) ----------------------------
__device__ __forceinline__ void red_add_v4(float* p, float4 v) {
    asm volatile("red.global.add.v4.f32 [%0], {%1,%2,%3,%4};"
                 :: "l"(p), "f"(v.x), "f"(v.y), "f"(v.z), "f"(v.w) : "memory");
}
__device__ __forceinline__ void red_add_v2(float* p, float2 v) {
    asm volatile("red.global.add.v2.f32 [%0], {%1,%2};"
                 :: "l"(p), "f"(v.x), "f"(v.y) : "memory");
}

// Fetch (src, dst) of edge e for either dtype.
__device__ __forceinline__ void load_edge(const int* ei, int is64, int e,
                                          int& src, int& dst) {
    if (is64) {
        const long long* e64 = reinterpret_cast<const long long*>(ei);
        src = (int)e64[e];
        dst = (int)e64[N_EDGES + e];
    } else {
        src = ei[e];
        dst = ei[N_EDGES + e];
    }
}

// ---------------- kernel 0: edge_index dtype probe ---------------------------
// int64 indices < 2^31 have zero high words at odd 32-bit positions; random
// int32 indices there are ~never all zero (P ~ (2e-5)^16).
__global__ void probe_dtype(const int* __restrict__ ei) {
    int all_zero = 1;
#pragma unroll
    for (int i = 0; i < 16; i++)
        if (ei[2 * i + 1] != 0) all_zero = 0;
    g_is64 = all_zero;
}

// ---------------- kernel 1: per-node projections for layer 1 ----------------
__global__ void layer1_node(const float* __restrict__ x,
                            const float* __restrict__ w_rel1,
                            const float* __restrict__ b_rel1,
                            const float* __restrict__ w_root1) {
    __shared__ float s_wr[IN_CH * HID];
    __shared__ float s_wo[IN_CH * HID];
    __shared__ float s_b[HID];
    for (int i = threadIdx.x; i < IN_CH * HID; i += blockDim.x) {
        s_wr[i] = w_rel1[i];
        s_wo[i] = w_root1[i];
    }
    if (threadIdx.x < HID) s_b[threadIdx.x] = b_rel1[threadIdx.x];
    __syncthreads();

    int node = blockIdx.x * blockDim.x + threadIdx.x;
    if (node >= N_NODES) return;

    float accy[HID], accr[HID];
#pragma unroll
    for (int j = 0; j < HID; j++) { accy[j] = 0.f; accr[j] = s_b[j]; }

    const float4* xr = reinterpret_cast<const float4*>(x + (size_t)node * IN_CH);
#pragma unroll
    for (int k4 = 0; k4 < IN_CH / 4; k4++) {
        float4 xv = __ldg(xr + k4);
        const float xs[4] = {xv.x, xv.y, xv.z, xv.w};
#pragma unroll
        for (int kk = 0; kk < 4; kk++) {
            int k = k4 * 4 + kk;
            float v = xs[kk];
#pragma unroll
            for (int j = 0; j < HID; j++) {
                accy[j] = fmaf(v, s_wr[k * HID + j], accy[j]);
                accr[j] = fmaf(v, s_wo[k * HID + j], accr[j]);
            }
        }
    }

    float4* y1p = reinterpret_cast<float4*>(g_y1   + (size_t)node * HID);
    float4* a1p = reinterpret_cast<float4*>(g_agg1 + (size_t)node * HID);
#pragma unroll
    for (int j = 0; j < HID / 4; j++) {
        y1p[j] = make_float4(accy[4*j], accy[4*j+1], accy[4*j+2], accy[4*j+3]);
        a1p[j] = make_float4(accr[4*j], accr[4*j+1], accr[4*j+2], accr[4*j+3]);
    }
}

// ---------------- kernel 2: edge scatter, layer 1 (16 floats/edge) ----------
// 4 threads per edge; each moves one float4. y1/agg1 are L2-resident (3.2MB).
__global__ void scatter1(const int* __restrict__ ei) {
    long long idx = (long long)blockIdx.x * blockDim.x + threadIdx.x;
    if (idx >= (long long)N_EDGES * 4) return;
    int e = (int)(idx >> 2);
    int q = (int)(idx & 3);
    int is64 = g_is64;
    int src, dst;
    load_edge(ei, is64, e, src, dst);
    if ((unsigned)src >= N_NODES || (unsigned)dst >= N_NODES) return;  // hardening
    float4 v = *reinterpret_cast<const float4*>(g_y1 + (size_t)src * HID + q * 4);
    red_add_v4(g_agg1 + (size_t)dst * HID + q * 4, v);
}

// ---------------- kernel 3: relu + per-node projections for layer 2 ---------
__global__ void layer2_node(const float* __restrict__ w_rel2,
                            const float* __restrict__ b_rel2,
                            const float* __restrict__ w_root2) {
    __shared__ float s_wr[HID * NCLS];
    __shared__ float s_wo[HID * NCLS];
    __shared__ float s_b[NCLS];
    for (int i = threadIdx.x; i < HID * NCLS; i += blockDim.x) {
        s_wr[i] = w_rel2[i];
        s_wo[i] = w_root2[i];
    }
    if (threadIdx.x < NCLS) s_b[threadIdx.x] = b_rel2[threadIdx.x];
    __syncthreads();

    int node = blockIdx.x * blockDim.x + threadIdx.x;
    if (node >= N_NODES) return;

    float h[HID];
    const float4* a1p = reinterpret_cast<const float4*>(g_agg1 + (size_t)node * HID);
#pragma unroll
    for (int j = 0; j < HID / 4; j++) {
        float4 v = a1p[j];
        h[4*j]   = fmaxf(v.x, 0.f);
        h[4*j+1] = fmaxf(v.y, 0.f);
        h[4*j+2] = fmaxf(v.z, 0.f);
        h[4*j+3] = fmaxf(v.w, 0.f);
    }

    float accy[NCLS], accr[NCLS];
#pragma unroll
    for (int j = 0; j < NCLS; j++) { accy[j] = 0.f; accr[j] = s_b[j]; }
#pragma unroll
    for (int k = 0; k < HID; k++) {
        float v = h[k];
#pragma unroll
        for (int j = 0; j < NCLS; j++) {
            accy[j] = fmaf(v, s_wr[k * NCLS + j], accy[j]);
            accr[j] = fmaf(v, s_wo[k * NCLS + j], accr[j]);
        }
    }

    float* y2p = g_y2   + (size_t)node * L2S;
    float* a2p = g_agg2 + (size_t)node * L2S;
#pragma unroll
    for (int j = 0; j < NCLS; j++) { y2p[j] = accy[j]; a2p[j] = accr[j]; }
}

// ---------------- kernel 4: edge scatter, layer 2 (10 floats/edge) ----------
// 3 threads per edge: q=0,1 -> float4 red; q=2 -> float2 red (floats 8..9).
__global__ void scatter2(const int* __restrict__ ei) {
    long long idx = (long long)blockIdx.x * blockDim.x + threadIdx.x;
    if (idx >= (long long)N_EDGES * 3) return;
    int e = (int)(idx / 3);
    int q = (int)(idx - (long long)e * 3);
    int is64 = g_is64;
    int src, dst;
    load_edge(ei, is64, e, src, dst);
    if ((unsigned)src >= N_NODES || (unsigned)dst >= N_NODES) return;  // hardening
    const float* yp = g_y2   + (size_t)src * L2S;
    float*       ap = g_agg2 + (size_t)dst * L2S;
    if (q < 2) {
        float4 v = *reinterpret_cast<const float4*>(yp + q * 4);
        red_add_v4(ap + q * 4, v);
    } else {
        float2 v = *reinterpret_cast<const float2*>(yp + 8);
        red_add_v2(ap + 8, v);
    }
}

// ---------------- kernel 5: log_softmax ------------------------------------
__global__ void lsm_kernel(float* __restrict__ out) {
    int node = blockIdx.x * blockDim.x + threadIdx.x;
    if (node >= N_NODES) return;
    const float* ap = g_agg2 + (size_t)node * L2S;
    float v[NCLS];
    float m = -3.4e38f;
#pragma unroll
    for (int j = 0; j < NCLS; j++) { v[j] = ap[j]; m = fmaxf(m, v[j]); }
    float s = 0.f;
#pragma unroll
    for (int j = 0; j < NCLS; j++) s += __expf(v[j] - m);
    float lse = __logf(s) + m;
    float* op = out + (size_t)node * NCLS;
#pragma unroll
    for (int j = 0; j < NCLS; j++) op[j] = v[j] - lse;
}

// ---------------- launch -----------------------------------------------------
extern "C" void kernel_launch(void* const* d_in, const int* in_sizes, int n_in,
                              void* d_out, int out_size) {
    const float* x       = (const float*)d_in[0];
    const int*   ei      = (const int*)d_in[1];   // dtype resolved by probe_dtype
    const float* w_rel1  = (const float*)d_in[2];
    const float* b_rel1  = (const float*)d_in[3];
    const float* w_root1 = (const float*)d_in[4];
    const float* w_rel2  = (const float*)d_in[5];
    const float* b_rel2  = (const float*)d_in[6];
    const float* w_root2 = (const float*)d_in[7];
    float* out = (float*)d_out;

    const int TB = 256;
    int nodeBlocks = (N_NODES + TB - 1) / TB;

    probe_dtype<<<1, 1>>>(ei);

    layer1_node<<<nodeBlocks, TB>>>(x, w_rel1, b_rel1, w_root1);

    long long s1threads = (long long)N_EDGES * 4;
    int s1blocks = (int)((s1threads + TB - 1) / TB);
    scatter1<<<s1blocks, TB>>>(ei);

    layer2_node<<<nodeBlocks, TB>>>(w_rel2, b_rel2, w_root2);

    long long s2threads = (long long)N_EDGES * 3;
    int s2blocks = (int)((s2threads + TB - 1) / TB);
    scatter2<<<s2blocks, TB>>>(ei);

    lsm_kernel<<<nodeBlocks, TB>>>(out);
}